// round 3
// baseline (speedup 1.0000x reference)
#include <cuda_runtime.h>
#include <cuda_bf16.h>
#include <cstdint>

// Problem constants
#define BATCH 4096
#define DIM   256
#define NREL  30
#define TILE_S 32        // samples per CTA tile
#define BLK_I  64        // M rows per SMEM block
#define NTHREADS 256
#define MAX_TILES 160    // >= 128 + 30 worst-case padding tiles

// Scratch (no allocations allowed): tile descriptors + padded sorted index list
__device__ int g_tile_rel[MAX_TILES];
__device__ int g_tile_start[MAX_TILES];
__device__ int g_sorted[MAX_TILES * TILE_S];
__device__ int g_ntiles;

// ---------------------------------------------------------------------------
// Kernel 1: bucket samples by relation, padded to TILE_S boundaries.
// Single CTA of 1024 threads. Dtype-robust: relation_ids may be int32 or
// int64 on disk. We read the buffer as int32 words; for little-endian int64
// with values in [0,30) every odd word is 0 — detect that and stride by 2.
// Detection only touches words [0, BATCH), in-bounds for both layouts.
// ---------------------------------------------------------------------------
__global__ void build_tiles_kernel(const int* __restrict__ ids32) {
    __shared__ int cnt[NREL];
    __shared__ int fill[NREL];
    __shared__ int pad_off[NREL + 1];
    __shared__ int odd_nonzero;
    int tid = threadIdx.x;

    if (tid < NREL) { cnt[tid] = 0; fill[tid] = 0; }
    if (tid == 0) odd_nonzero = 0;
    __syncthreads();

    // dtype detection: any nonzero odd word => int32 data
    for (int i = tid; i < BATCH / 2; i += 1024)
        if (ids32[2 * i + 1] != 0) odd_nonzero = 1;
    __syncthreads();

    const int stride = odd_nonzero ? 1 : 2;   // int32 : int64 (low word)

    for (int i = tid; i < BATCH; i += 1024) {
        int r = ids32[i * stride];
        if ((unsigned)r < NREL) atomicAdd(&cnt[r], 1);
    }
    __syncthreads();

    if (tid == 0) {
        int off = 0, t = 0;
        for (int r = 0; r < NREL; r++) {
            pad_off[r] = off;
            int ntile = (cnt[r] + TILE_S - 1) / TILE_S;
            for (int k = 0; k < ntile; k++) {
                g_tile_rel[t]   = r;
                g_tile_start[t] = off + k * TILE_S;
                t++;
            }
            off += ntile * TILE_S;
        }
        pad_off[NREL] = off;
        g_ntiles = t;
    }
    __syncthreads();

    // Reset padded list to -1, then scatter
    for (int i = tid; i < MAX_TILES * TILE_S; i += 1024)
        g_sorted[i] = -1;
    __syncthreads();

    for (int i = tid; i < BATCH; i += 1024) {
        int r = ids32[i * stride];
        if ((unsigned)r < NREL) {
            int p = pad_off[r] + atomicAdd(&fill[r], 1);
            g_sorted[p] = i;
        }
    }
}

// ---------------------------------------------------------------------------
// Kernel 2: per-tile bilinear scores.
// CTA = (relation r, 32 samples). M_r streamed through SMEM in 64-row blocks.
// Thread tile: 8 samples x 4 columns of y = h^T M; epilogue folds in t and
// reduces deterministically (fixed order) across the 64 column groups.
// ---------------------------------------------------------------------------
extern __shared__ float smem[];

__global__ __launch_bounds__(NTHREADS, 1)
void bilinear_kernel(const float* __restrict__ head,
                     const float* __restrict__ tail,
                     const float* __restrict__ relmat,
                     float* __restrict__ out) {
    int b = blockIdx.x;
    if (b >= g_ntiles) return;

    float* M_sm = smem;                       // BLK_I * DIM      = 16384 f
    float* h_sm = M_sm + BLK_I * DIM;         // TILE_S * DIM     =  8192 f
    float* t_sm = h_sm + TILE_S * DIM;        // TILE_S * DIM     =  8192 f
    float* red  = t_sm + TILE_S * DIM;        // TILE_S * 64      =  2048 f
    int*  s_idx = (int*)(red + TILE_S * 64);  // TILE_S ints

    int tid = threadIdx.x;
    int r     = g_tile_rel[b];
    int start = g_tile_start[b];

    if (tid < TILE_S) s_idx[tid] = g_sorted[start + tid];
    __syncthreads();

    // Load h and t tiles (32 rows x 256 floats each), vectorized.
    for (int e = tid; e < TILE_S * (DIM / 4); e += NTHREADS) {
        int s = e >> 6;          // / (DIM/4)
        int c = e & 63;          // % (DIM/4)
        int gi = s_idx[s];
        float4 hv = make_float4(0.f, 0.f, 0.f, 0.f);
        float4 tv = make_float4(0.f, 0.f, 0.f, 0.f);
        if (gi >= 0) {
            hv = reinterpret_cast<const float4*>(head + (size_t)gi * DIM)[c];
            tv = reinterpret_cast<const float4*>(tail + (size_t)gi * DIM)[c];
        }
        reinterpret_cast<float4*>(h_sm + s * DIM)[c] = hv;
        reinterpret_cast<float4*>(t_sm + s * DIM)[c] = tv;
    }

    const float* M = relmat + (size_t)r * DIM * DIM;

    int jg = tid & 63;           // column group 0..63
    int sg = tid >> 6;           // sample group 0..3
    int j0 = jg * 4;
    int s0 = sg * 8;

    float acc[8][4];
    #pragma unroll
    for (int s = 0; s < 8; s++)
        #pragma unroll
        for (int c = 0; c < 4; c++) acc[s][c] = 0.f;

    #pragma unroll
    for (int blk = 0; blk < DIM / BLK_I; blk++) {
        __syncthreads();   // protects M_sm reuse; also orders h/t tile loads (blk 0)

        // Load M block: BLK_I x DIM floats = 4096 float4, 16 per thread
        const float4* Mg = reinterpret_cast<const float4*>(M + blk * BLK_I * DIM);
        float4* Ms4 = reinterpret_cast<float4*>(M_sm);
        #pragma unroll
        for (int k = 0; k < 16; k++)
            Ms4[tid + k * NTHREADS] = Mg[tid + k * NTHREADS];
        __syncthreads();

        #pragma unroll 4
        for (int il = 0; il < BLK_I; il++) {
            float4 m = *reinterpret_cast<const float4*>(M_sm + il * DIM + j0);
            int i = blk * BLK_I + il;
            #pragma unroll
            for (int s = 0; s < 8; s++) {
                float hv = h_sm[(s0 + s) * DIM + i];   // broadcast within warp
                acc[s][0] = fmaf(hv, m.x, acc[s][0]);
                acc[s][1] = fmaf(hv, m.y, acc[s][1]);
                acc[s][2] = fmaf(hv, m.z, acc[s][2]);
                acc[s][3] = fmaf(hv, m.w, acc[s][3]);
            }
        }
    }

    // Epilogue: fold in t, reduce per-sample across column groups (fixed order).
    #pragma unroll
    for (int s = 0; s < 8; s++) {
        const float4 tv = *reinterpret_cast<const float4*>(t_sm + (s0 + s) * DIM + j0);
        float p = acc[s][0] * tv.x + acc[s][1] * tv.y
                + acc[s][2] * tv.z + acc[s][3] * tv.w;
        red[(s0 + s) * 64 + jg] = p;
    }
    __syncthreads();

    if (tid < TILE_S) {
        float sum = 0.f;
        #pragma unroll
        for (int g = 0; g < 64; g++) sum += red[tid * 64 + g];
        int gi = s_idx[tid];
        if (gi >= 0) out[gi] = sum;
    }
}

// ---------------------------------------------------------------------------
// Launch: resolve input slots by element count (robust to ordering).
//   4096            -> relation_ids
//   NREL*DIM*DIM    -> relation_matrices
//   BATCH*DIM (x2)  -> head, tail (in original order)
// ---------------------------------------------------------------------------
extern "C" void kernel_launch(void* const* d_in, const int* in_sizes, int n_in,
                              void* d_out, int out_size) {
    const float* head = nullptr;
    const float* tail = nullptr;
    const int*   ids  = nullptr;
    const float* relmat = nullptr;

    for (int i = 0; i < n_in; i++) {
        if (in_sizes[i] == BATCH)                 ids    = (const int*)d_in[i];
        else if (in_sizes[i] == NREL * DIM * DIM) relmat = (const float*)d_in[i];
        else if (in_sizes[i] == BATCH * DIM) {
            if (!head) head = (const float*)d_in[i];
            else       tail = (const float*)d_in[i];
        }
    }
    float* out = (float*)d_out;

    const int smem_bytes = (BLK_I * DIM + 2 * TILE_S * DIM + TILE_S * 64) * sizeof(float)
                         + TILE_S * sizeof(int);

    cudaFuncSetAttribute(bilinear_kernel,
                         cudaFuncAttributeMaxDynamicSharedMemorySize, smem_bytes);

    build_tiles_kernel<<<1, 1024>>>(ids);
    bilinear_kernel<<<MAX_TILES, NTHREADS, smem_bytes>>>(head, tail, relmat, out);
}

// round 4
// speedup vs baseline: 1.0244x; 1.0244x over previous
#include <cuda_runtime.h>
#include <cuda_bf16.h>
#include <cstdint>

// Problem constants
#define BATCH 4096
#define DIM   256
#define NREL  30
#define TILE_S 32        // samples per tile
#define IHALF  128       // i-rows per work unit (tile split in 2)
#define BLK_I  64        // M rows per SMEM block (2 blocks/unit, double-buffered)
#define NTHREADS 256
#define MAX_TILES 160    // >= 128 + 30 worst-case padding tiles

__device__ int g_tile_rel[MAX_TILES];
__device__ int g_tile_start[MAX_TILES];
__device__ int g_sorted[MAX_TILES * TILE_S];
__device__ int g_ntiles;

// ---------------------------------------------------------------------------
// Kernel 1: bucket samples by relation (padded to TILE_S) + zero the output.
// relation_ids dtype-robust (int32 vs int64 low-word detection).
// ---------------------------------------------------------------------------
__global__ void build_tiles_kernel(const int* __restrict__ ids32,
                                   float* __restrict__ out) {
    __shared__ int cnt[NREL];
    __shared__ int fill[NREL];
    __shared__ int pad_off[NREL + 1];
    __shared__ int odd_nonzero;
    int tid = threadIdx.x;

    for (int i = tid; i < BATCH; i += 1024) out[i] = 0.0f;

    if (tid < NREL) { cnt[tid] = 0; fill[tid] = 0; }
    if (tid == 0) odd_nonzero = 0;
    __syncthreads();

    for (int i = tid; i < BATCH / 2; i += 1024)
        if (ids32[2 * i + 1] != 0) odd_nonzero = 1;
    __syncthreads();

    const int stride = odd_nonzero ? 1 : 2;   // int32 : int64 (low word)

    for (int i = tid; i < BATCH; i += 1024) {
        int r = ids32[i * stride];
        if ((unsigned)r < NREL) atomicAdd(&cnt[r], 1);
    }
    __syncthreads();

    if (tid == 0) {
        int off = 0, t = 0;
        for (int r = 0; r < NREL; r++) {
            pad_off[r] = off;
            int ntile = (cnt[r] + TILE_S - 1) / TILE_S;
            for (int k = 0; k < ntile; k++) {
                g_tile_rel[t]   = r;
                g_tile_start[t] = off + k * TILE_S;
                t++;
            }
            off += ntile * TILE_S;
        }
        pad_off[NREL] = off;
        g_ntiles = t;
    }
    __syncthreads();

    for (int i = tid; i < MAX_TILES * TILE_S; i += 1024)
        g_sorted[i] = -1;
    __syncthreads();

    for (int i = tid; i < BATCH; i += 1024) {
        int r = ids32[i * stride];
        if ((unsigned)r < NREL) {
            int p = pad_off[r] + atomicAdd(&fill[r], 1);
            g_sorted[p] = i;
        }
    }
}

// ---------------------------------------------------------------------------
// f32x2 helpers (Blackwell packed fp32)
// ---------------------------------------------------------------------------
__device__ __forceinline__ unsigned long long pack2(float lo, float hi) {
    unsigned long long r;
    asm("mov.b64 %0, {%1, %2};" : "=l"(r) : "f"(lo), "f"(hi));
    return r;
}
__device__ __forceinline__ void unpack2(unsigned long long v, float& lo, float& hi) {
    asm("mov.b64 {%0, %1}, %2;" : "=f"(lo), "=f"(hi) : "l"(v));
}
__device__ __forceinline__ void fma2(unsigned long long& d,
                                     unsigned long long a, unsigned long long b) {
    asm("fma.rn.f32x2 %0, %1, %2, %0;" : "+l"(d) : "l"(a), "l"(b));
}
__device__ __forceinline__ void cpasync16(uint32_t dst_smem, const void* src) {
    asm volatile("cp.async.cg.shared.global [%0], [%1], 16;" :: "r"(dst_smem), "l"(src));
}

// ---------------------------------------------------------------------------
// Kernel 2: unit = (tile, i-half). 320 CTAs (~314 real -> 3 balanced-ish waves).
// Thread tile: 8 samples x 8 cols via f32x2 (samples packed). Two 128-thread
// "teams" split the i rows. M double-buffered with cp.async. Partial scores
// combined with atomicAdd (2 adds, commutative -> deterministic).
// ---------------------------------------------------------------------------
extern __shared__ float smem[];

__global__ __launch_bounds__(NTHREADS, 1)
void bilinear_kernel(const float* __restrict__ head,
                     const float* __restrict__ tail,
                     const float* __restrict__ relmat,
                     float* __restrict__ out) {
    int b    = blockIdx.x;
    int tile = b >> 1;
    int ih   = b & 1;
    if (tile >= g_ntiles) return;

    float* M0  = smem;                         // 2 * 64 * 256 = 32768 f
    float* hT  = M0 + 2 * BLK_I * DIM;         // 128 * 32     =  4096 f (transposed)
    float* Ts  = hT + IHALF * TILE_S;          // 32 * 256     =  8192 f
    float* red = Ts + TILE_S * DIM;            // 32 * 64      =  2048 f
    int* s_idx = (int*)(red + TILE_S * 64);    // 32 ints

    int tid = threadIdx.x;
    int r     = g_tile_rel[tile];
    int start = g_tile_start[tile];
    if (tid < TILE_S) s_idx[tid] = g_sorted[start + tid];
    __syncthreads();

    const float* M = relmat + (size_t)r * DIM * DIM + (size_t)ih * IHALF * DIM;

    // Kick off cp.async for M block 0 (overlaps the h/t global loads below)
    {
        uint32_t mdst = (uint32_t)__cvta_generic_to_shared(M0);
        const float4* Mg = (const float4*)M;
        #pragma unroll
        for (int k = 0; k < 16; k++) {
            int idx = tid + k * NTHREADS;          // < 4096 float4
            cpasync16(mdst + idx * 16, Mg + idx);
        }
        asm volatile("cp.async.commit_group;");
    }

    // h tile, TRANSPOSED: hT[i_local * 32 + s]. s = lane -> conflict-free STS.
    for (int e = tid; e < TILE_S * (IHALF / 4); e += NTHREADS) {   // 1024
        int s = e & 31, c = e >> 5;
        int gi = s_idx[s];
        float4 hv = make_float4(0.f, 0.f, 0.f, 0.f);
        if (gi >= 0)
            hv = ((const float4*)(head + (size_t)gi * DIM + ih * IHALF))[c];
        hT[(4 * c + 0) * TILE_S + s] = hv.x;
        hT[(4 * c + 1) * TILE_S + s] = hv.y;
        hT[(4 * c + 2) * TILE_S + s] = hv.z;
        hT[(4 * c + 3) * TILE_S + s] = hv.w;
    }
    // t tile, row-major: c = lane -> coalesced LDG + conflict-free STS.128
    for (int e = tid; e < TILE_S * (DIM / 4); e += NTHREADS) {     // 2048
        int c = e & 63, s = e >> 6;
        int gi = s_idx[s];
        float4 tv = make_float4(0.f, 0.f, 0.f, 0.f);
        if (gi >= 0)
            tv = ((const float4*)(tail + (size_t)gi * DIM))[c];
        ((float4*)(Ts + s * DIM))[c] = tv;
    }

    asm volatile("cp.async.wait_group 0;");
    __syncthreads();

    // Thread mapping: jg = lane (32 j-groups of 4, at j and j+128);
    // warp w: team = w>>2 (i-split), sg = w&3 (8 samples).
    int jg   = tid & 31;
    int wid  = tid >> 5;
    int team = wid >> 2;
    int sg   = wid & 3;
    int s0   = sg * 8;

    unsigned long long acc[4][8];   // [sample-pair][j]  (8 samples x 8 cols)
    #pragma unroll
    for (int sp = 0; sp < 4; sp++)
        #pragma unroll
        for (int k = 0; k < 8; k++) acc[sp][k] = 0ull;

    #pragma unroll
    for (int blk = 0; blk < 2; blk++) {
        if (blk == 0) {
            // prefetch M block 1 into buffer 1
            uint32_t mdst = (uint32_t)__cvta_generic_to_shared(M0 + BLK_I * DIM);
            const float4* Mg = (const float4*)(M + BLK_I * DIM);
            #pragma unroll
            for (int k = 0; k < 16; k++) {
                int idx = tid + k * NTHREADS;
                cpasync16(mdst + idx * 16, Mg + idx);
            }
            asm volatile("cp.async.commit_group;");
        }

        const float* Mb = M0 + blk * BLK_I * DIM;

        #pragma unroll 4
        for (int il32 = 0; il32 < 32; il32++) {
            int il = team * 32 + il32;               // row within block
            float4 mA = *(const float4*)(Mb + il * DIM + jg * 4);
            float4 mB = *(const float4*)(Mb + il * DIM + 128 + jg * 4);
            int ig = blk * BLK_I + il;               // row within i-half

            unsigned long long h2[4];
            #pragma unroll
            for (int sp = 0; sp < 4; sp++)
                h2[sp] = *(const unsigned long long*)(hT + ig * TILE_S + s0 + 2 * sp);

            unsigned long long md[8];
            md[0] = pack2(mA.x, mA.x); md[1] = pack2(mA.y, mA.y);
            md[2] = pack2(mA.z, mA.z); md[3] = pack2(mA.w, mA.w);
            md[4] = pack2(mB.x, mB.x); md[5] = pack2(mB.y, mB.y);
            md[6] = pack2(mB.z, mB.z); md[7] = pack2(mB.w, mB.w);

            #pragma unroll
            for (int sp = 0; sp < 4; sp++)
                #pragma unroll
                for (int k = 0; k < 8; k++)
                    fma2(acc[sp][k], h2[sp], md[k]);
        }

        if (blk == 0) {
            asm volatile("cp.async.wait_group 0;");
            __syncthreads();
        }
    }

    // Epilogue: fold in t, per-(s, team, jg) partials, then reduce 64 groups.
    #pragma unroll
    for (int sp = 0; sp < 4; sp++) {
        int sA = s0 + 2 * sp, sB = sA + 1;
        float4 taA = *(const float4*)(Ts + sA * DIM + jg * 4);
        float4 taB = *(const float4*)(Ts + sA * DIM + 128 + jg * 4);
        float4 tbA = *(const float4*)(Ts + sB * DIM + jg * 4);
        float4 tbB = *(const float4*)(Ts + sB * DIM + 128 + jg * 4);
        float pA = 0.f, pB = 0.f, lo, hi;
        unpack2(acc[sp][0], lo, hi); pA += lo * taA.x; pB += hi * tbA.x;
        unpack2(acc[sp][1], lo, hi); pA += lo * taA.y; pB += hi * tbA.y;
        unpack2(acc[sp][2], lo, hi); pA += lo * taA.z; pB += hi * tbA.z;
        unpack2(acc[sp][3], lo, hi); pA += lo * taA.w; pB += hi * tbA.w;
        unpack2(acc[sp][4], lo, hi); pA += lo * taB.x; pB += hi * tbB.x;
        unpack2(acc[sp][5], lo, hi); pA += lo * taB.y; pB += hi * tbB.y;
        unpack2(acc[sp][6], lo, hi); pA += lo * taB.z; pB += hi * tbB.z;
        unpack2(acc[sp][7], lo, hi); pA += lo * taB.w; pB += hi * tbB.w;
        red[sA * 64 + team * 32 + jg] = pA;
        red[sB * 64 + team * 32 + jg] = pB;
    }
    __syncthreads();

    if (tid < TILE_S) {
        int s = tid;
        float sum = 0.f;
        #pragma unroll
        for (int g = 0; g < 64; g++)
            sum += red[s * 64 + ((g + s) & 63)];   // rotated: conflict-free
        int gi = s_idx[s];
        if (gi >= 0) atomicAdd(&out[gi], sum);     // 2 commutative adds
    }
}

// ---------------------------------------------------------------------------
// Launch: resolve input slots by element count.
// ---------------------------------------------------------------------------
extern "C" void kernel_launch(void* const* d_in, const int* in_sizes, int n_in,
                              void* d_out, int out_size) {
    const float* head = nullptr;
    const float* tail = nullptr;
    const int*   ids  = nullptr;
    const float* relmat = nullptr;

    for (int i = 0; i < n_in; i++) {
        if (in_sizes[i] == BATCH)                 ids    = (const int*)d_in[i];
        else if (in_sizes[i] == NREL * DIM * DIM) relmat = (const float*)d_in[i];
        else if (in_sizes[i] == BATCH * DIM) {
            if (!head) head = (const float*)d_in[i];
            else       tail = (const float*)d_in[i];
        }
    }
    float* out = (float*)d_out;

    const int smem_bytes =
        (2 * BLK_I * DIM + IHALF * TILE_S + TILE_S * DIM + TILE_S * 64) * sizeof(float)
        + TILE_S * sizeof(int);

    cudaFuncSetAttribute(bilinear_kernel,
                         cudaFuncAttributeMaxDynamicSharedMemorySize, smem_bytes);

    build_tiles_kernel<<<1, 1024>>>(ids, out);
    bilinear_kernel<<<MAX_TILES * 2, NTHREADS, smem_bytes>>>(head, tail, relmat, out);
}

// round 6
// speedup vs baseline: 1.1693x; 1.1414x over previous
#include <cuda_runtime.h>
#include <cuda_bf16.h>
#include <cstdint>

#define BATCH 4096
#define DIM   256
#define NREL  30
#define GS    32          // samples per group (MMA M dim)
#define MAXG  160         // >= 30 + 4096/32
#define NTH   256
#define KC    32          // K rows per pipeline chunk
#define NCHUNKS 8         // DIM / KC
#define AST   40          // A smem row stride (halves): 32 + 8 pad
#define BST   264         // B smem row stride (halves): 256 + 8 pad
#define TST   260         // tT row stride (floats)

// SMEM byte offsets (dynamic smem)
#define OFF_SIDX 0                        // 32 ints
#define OFF_RED  128                      // 128 floats (4 n-warps x 32 rows)
#define OFF_TT   640                      // 32 x 260 floats = 33280
#define OFF_A    33920                    // [2 buf][2 mat][32 s][40 h] *2B = 10240
#define OFF_B    44160                    // [2 buf][2 mat][32 k][264 h]*2B = 67584
#define SMEM_BYTES 111744

// ---- device scratch ----
__device__ int g_grp_rel[MAXG];
__device__ int g_grp_start[MAXG];
__device__ int g_sorted[MAXG * GS];
__device__ int g_ngrp;
__device__ __nv_bfloat16 g_Mb[NREL * DIM * DIM];
__device__ __nv_bfloat16 g_Ms[NREL * DIM * DIM];
__device__ __nv_bfloat16 g_Hb[BATCH * DIM];
__device__ __nv_bfloat16 g_Hs[BATCH * DIM];

// ---- helpers ----
__device__ __forceinline__ uint32_t smem_u32(const void* p) {
    uint32_t a;
    asm("{ .reg .u64 t; cvta.to.shared.u64 t, %1; cvt.u32.u64 %0, t; }" : "=r"(a) : "l"(p));
    return a;
}
__device__ __forceinline__ void cpasync16(uint32_t dst, const void* src) {
    asm volatile("cp.async.cg.shared.global [%0], [%1], 16;" :: "r"(dst), "l"(src));
}
__device__ __forceinline__ void sts16_zero(uint32_t dst) {
    asm volatile("st.shared.v4.b32 [%0], {%1,%1,%1,%1};" :: "r"(dst), "r"(0u) : "memory");
}
__device__ __forceinline__ void ldm_x4(uint32_t* r, uint32_t addr) {
    asm volatile("ldmatrix.sync.aligned.m8n8.x4.shared.b16 {%0,%1,%2,%3}, [%4];"
                 : "=r"(r[0]), "=r"(r[1]), "=r"(r[2]), "=r"(r[3]) : "r"(addr));
}
__device__ __forceinline__ void ldm_x4_t(uint32_t* r, uint32_t addr) {
    asm volatile("ldmatrix.sync.aligned.m8n8.x4.trans.shared.b16 {%0,%1,%2,%3}, [%4];"
                 : "=r"(r[0]), "=r"(r[1]), "=r"(r[2]), "=r"(r[3]) : "r"(addr));
}
__device__ __forceinline__ void mma_bf16(float* c, const uint32_t* a, const uint32_t* b) {
    asm volatile("mma.sync.aligned.m16n8k16.row.col.f32.bf16.bf16.f32 "
                 "{%0,%1,%2,%3}, {%4,%5,%6,%7}, {%8,%9}, {%0,%1,%2,%3};"
                 : "+f"(c[0]), "+f"(c[1]), "+f"(c[2]), "+f"(c[3])
                 : "r"(a[0]), "r"(a[1]), "r"(a[2]), "r"(a[3]), "r"(b[0]), "r"(b[1]));
}

// ---------------------------------------------------------------------------
// Kernel A: split fp32 -> (big, small) bf16 for M and H.
// ---------------------------------------------------------------------------
__global__ void convert_kernel(const float* __restrict__ head,
                               const float* __restrict__ relmat) {
    int tid = blockIdx.x * blockDim.x + threadIdx.x;
    int nthr = gridDim.x * blockDim.x;

    const int NM2 = NREL * DIM * DIM / 2;
    const float2* M2 = (const float2*)relmat;
    __nv_bfloat162* Mb2 = (__nv_bfloat162*)g_Mb;
    __nv_bfloat162* Ms2 = (__nv_bfloat162*)g_Ms;
    for (int e = tid; e < NM2; e += nthr) {
        float2 v = M2[e];
        __nv_bfloat16 bx = __float2bfloat16(v.x), by = __float2bfloat16(v.y);
        __nv_bfloat16 sx = __float2bfloat16(v.x - __bfloat162float(bx));
        __nv_bfloat16 sy = __float2bfloat16(v.y - __bfloat162float(by));
        Mb2[e] = __nv_bfloat162(bx, by);
        Ms2[e] = __nv_bfloat162(sx, sy);
    }
    const int NH2 = BATCH * DIM / 2;
    const float2* H2 = (const float2*)head;
    __nv_bfloat162* Hb2 = (__nv_bfloat162*)g_Hb;
    __nv_bfloat162* Hs2 = (__nv_bfloat162*)g_Hs;
    for (int e = tid; e < NH2; e += nthr) {
        float2 v = H2[e];
        __nv_bfloat16 bx = __float2bfloat16(v.x), by = __float2bfloat16(v.y);
        __nv_bfloat16 sx = __float2bfloat16(v.x - __bfloat162float(bx));
        __nv_bfloat16 sy = __float2bfloat16(v.y - __bfloat162float(by));
        Hb2[e] = __nv_bfloat162(bx, by);
        Hs2[e] = __nv_bfloat162(sx, sy);
    }
}

// ---------------------------------------------------------------------------
// Kernel B: group samples by relation, padded to GS. int32/int64-robust ids.
// ---------------------------------------------------------------------------
__global__ void build_groups_kernel(const int* __restrict__ ids32) {
    __shared__ int cnt[NREL];
    __shared__ int fill[NREL];
    __shared__ int pad_off[NREL + 1];
    __shared__ int odd_nonzero;
    int tid = threadIdx.x;

    if (tid < NREL) { cnt[tid] = 0; fill[tid] = 0; }
    if (tid == 0) odd_nonzero = 0;
    __syncthreads();
    for (int i = tid; i < BATCH / 2; i += 1024)
        if (ids32[2 * i + 1] != 0) odd_nonzero = 1;
    __syncthreads();
    const int stride = odd_nonzero ? 1 : 2;   // int32 : int64 low word

    for (int i = tid; i < BATCH; i += 1024) {
        int r = ids32[i * stride];
        if ((unsigned)r < NREL) atomicAdd(&cnt[r], 1);
    }
    __syncthreads();

    if (tid == 0) {
        int off = 0, t = 0;
        for (int r = 0; r < NREL; r++) {
            pad_off[r] = off;
            int ng = (cnt[r] + GS - 1) / GS;
            for (int k = 0; k < ng; k++) {
                g_grp_rel[t] = r;
                g_grp_start[t] = off + k * GS;
                t++;
            }
            off += ng * GS;
        }
        g_ngrp = t;
    }
    __syncthreads();

    for (int i = tid; i < MAXG * GS; i += 1024) g_sorted[i] = -1;
    __syncthreads();

    for (int i = tid; i < BATCH; i += 1024) {
        int r = ids32[i * stride];
        if ((unsigned)r < NREL) {
            int p = pad_off[r] + atomicAdd(&fill[r], 1);
            g_sorted[p] = i;
        }
    }
}

// ---------------------------------------------------------------------------
// Kernel C: one CTA per group. Y[32,256] = H*M via 3-pass bf16 mma.sync,
// epilogue folds t and reduces deterministically. 8 warps: 2 m-tiles x 4 n-warps.
// ---------------------------------------------------------------------------
extern __shared__ char smem[];

__device__ __forceinline__ void issue_chunk(
    int kc, int tid, uint32_t sb, const int* s_idx,
    const __nv_bfloat16* MbP, const __nv_bfloat16* MsP) {
    int buf = kc & 1;
    // A: 2 mats x 32 rows x 4 u (16B each) = 256 transfers, one per thread
    {
        int mat = tid >> 7, idx = tid & 127;
        int s = idx >> 2, u = idx & 3;
        int gi = s_idx[s];
        uint32_t dst = sb + OFF_A + (uint32_t)(((buf * 2 + mat) * GS * AST + s * AST + u * 8) * 2);
        if (gi >= 0)
            cpasync16(dst, (mat ? g_Hs : g_Hb) + (size_t)gi * DIM + kc * KC + u * 8);
        else
            sts16_zero(dst);
    }
    // B: 2 mats x 32 k-rows x 32 u = 2048 transfers, 8 per thread
    #pragma unroll
    for (int k = 0; k < 8; k++) {
        int e = tid + k * NTH;
        int mat = e >> 10, idx = e & 1023;
        int kr = idx >> 5, u = idx & 31;
        uint32_t dst = sb + OFF_B + (uint32_t)(((buf * 2 + mat) * KC * BST + kr * BST + u * 8) * 2);
        cpasync16(dst, (mat ? MsP : MbP) + (size_t)(kc * KC + kr) * DIM + u * 8);
    }
    asm volatile("cp.async.commit_group;" ::: "memory");
}

__global__ __launch_bounds__(NTH, 1)
void mma_kernel(const float* __restrict__ tail, float* __restrict__ out) {
    int g = blockIdx.x;
    if (g >= g_ngrp) return;

    int tid = threadIdx.x, wid = tid >> 5, l = tid & 31;
    int mw = wid & 1;          // m-tile (16 rows)
    int nw = wid >> 1;         // n-warp (64 cols)
    uint32_t sb = smem_u32(smem);
    int* s_idx = (int*)(smem + OFF_SIDX);
    float* red = (float*)(smem + OFF_RED);
    float* tT  = (float*)(smem + OFF_TT);

    int r = g_grp_rel[g];
    int start = g_grp_start[g];
    if (tid < GS) s_idx[tid] = g_sorted[start + tid];
    __syncthreads();

    const __nv_bfloat16* MbP = g_Mb + (size_t)r * DIM * DIM;
    const __nv_bfloat16* MsP = g_Ms + (size_t)r * DIM * DIM;

    issue_chunk(0, tid, sb, s_idx, MbP, MsP);
    issue_chunk(1, tid, sb, s_idx, MbP, MsP);

    // t tile (fp32), zero-filled for padded rows; overlaps cp.async flight
    for (int e = tid; e < GS * (DIM / 4); e += NTH) {   // 2048
        int s = e >> 6, cc = e & 63;
        int gi = s_idx[s];
        float4 tv = make_float4(0.f, 0.f, 0.f, 0.f);
        if (gi >= 0) tv = ((const float4*)(tail + (size_t)gi * DIM))[cc];
        *(float4*)(tT + s * TST + cc * 4) = tv;
    }

    float c[8][4];
    #pragma unroll
    for (int nf = 0; nf < 8; nf++)
        #pragma unroll
        for (int k = 0; k < 4; k++) c[nf][k] = 0.f;

    // lane-invariant frag addressing pieces
    uint32_t a_row  = mw * 16 + (l & 15);
    uint32_t a_koff = (uint32_t)((l >> 4) << 3);
    uint32_t b_krow = (uint32_t)(l & 15);
    uint32_t b_ncol = (uint32_t)(nw * 64 + ((l >> 4) << 3));

    for (int kc = 0; kc < NCHUNKS; kc++) {
        if (kc == NCHUNKS - 1)
            asm volatile("cp.async.wait_group 0;" ::: "memory");
        else
            asm volatile("cp.async.wait_group 1;" ::: "memory");
        __syncthreads();

        int buf = kc & 1;
        uint32_t Ab0 = sb + OFF_A + (uint32_t)((buf * 2 + 0) * GS * AST * 2);
        uint32_t Ab1 = sb + OFF_A + (uint32_t)((buf * 2 + 1) * GS * AST * 2);
        uint32_t Bb0 = sb + OFF_B + (uint32_t)((buf * 2 + 0) * KC * BST * 2);
        uint32_t Bb1 = sb + OFF_B + (uint32_t)((buf * 2 + 1) * KC * BST * 2);

        #pragma unroll
        for (int ks = 0; ks < KC / 16; ks++) {
            uint32_t aB[4], aS[4];
            uint32_t ka = ks * 16 + a_koff;
            ldm_x4(aB, Ab0 + (a_row * AST + ka) * 2);
            ldm_x4(aS, Ab1 + (a_row * AST + ka) * 2);
            #pragma unroll
            for (int nt = 0; nt < 4; nt++) {
                uint32_t bB[4], bS[4];
                uint32_t boff = ((ks * 16 + b_krow) * BST + b_ncol + nt * 16) * 2;
                ldm_x4_t(bB, Bb0 + boff);
                ldm_x4_t(bS, Bb1 + boff);
                mma_bf16(c[2 * nt],     aB, bB);
                mma_bf16(c[2 * nt + 1], aB, bB + 2);
                mma_bf16(c[2 * nt],     aB, bS);
                mma_bf16(c[2 * nt + 1], aB, bS + 2);
                mma_bf16(c[2 * nt],     aS, bB);
                mma_bf16(c[2 * nt + 1], aS, bB + 2);
            }
        }
        __syncthreads();
        if (kc + 2 < NCHUNKS) issue_chunk(kc + 2, tid, sb, s_idx, MbP, MsP);
    }

    // ---- epilogue: fold t, quad-reduce, deterministic combine ----
    int q = l & 3, a = l >> 2;
    int row0 = mw * 16 + a, row1 = row0 + 8;
    float p0 = 0.f, p1 = 0.f;
    #pragma unroll
    for (int nf = 0; nf < 8; nf++) {
        int j = nw * 64 + nf * 8 + q * 2;
        p0 += c[nf][0] * tT[row0 * TST + j] + c[nf][1] * tT[row0 * TST + j + 1];
        p1 += c[nf][2] * tT[row1 * TST + j] + c[nf][3] * tT[row1 * TST + j + 1];
    }
    p0 += __shfl_xor_sync(0xFFFFFFFF, p0, 1);
    p0 += __shfl_xor_sync(0xFFFFFFFF, p0, 2);
    p1 += __shfl_xor_sync(0xFFFFFFFF, p1, 1);
    p1 += __shfl_xor_sync(0xFFFFFFFF, p1, 2);
    if (q == 0) {
        red[nw * 32 + row0] = p0;
        red[nw * 32 + row1] = p1;
    }
    __syncthreads();

    if (tid < GS) {
        int gi = s_idx[tid];
        if (gi >= 0)
            out[gi] = red[tid] + red[32 + tid] + red[64 + tid] + red[96 + tid];
    }
}

// ---------------------------------------------------------------------------
// Launch: resolve input slots by element count.
// ---------------------------------------------------------------------------
extern "C" void kernel_launch(void* const* d_in, const int* in_sizes, int n_in,
                              void* d_out, int out_size) {
    const float* head = nullptr;
    const float* tail = nullptr;
    const int*   ids  = nullptr;
    const float* relmat = nullptr;

    for (int i = 0; i < n_in; i++) {
        if (in_sizes[i] == BATCH)                 ids    = (const int*)d_in[i];
        else if (in_sizes[i] == NREL * DIM * DIM) relmat = (const float*)d_in[i];
        else if (in_sizes[i] == BATCH * DIM) {
            if (!head) head = (const float*)d_in[i];
            else       tail = (const float*)d_in[i];
        }
    }
    float* out = (float*)d_out;

    cudaFuncSetAttribute(mma_kernel,
                         cudaFuncAttributeMaxDynamicSharedMemorySize, SMEM_BYTES);

    convert_kernel<<<256, 256>>>(head, relmat);
    build_groups_kernel<<<1, 1024>>>(ids);
    mma_kernel<<<MAXG, NTH, SMEM_BYTES>>>(tail, out);
}